// round 14
// baseline (speedup 1.0000x reference)
#include <cuda_runtime.h>
#include <cuda_bf16.h>
#include <cstdint>

// Problem constants (fixed by the reference)
#define EMB    64
#define HEADS  8
#define DIMI   20
#define NQ     4116                  // DIMI + 16*16*16
#define ROWF4  1029                  // 4116 / 4
#define TABR   63                    // 2*CAP - 1
#define INVT   0.125f                // 64^-0.5

#define NPROJ  (3 * HEADS * TABR)    // 1512
#define NCROSS (HEADS * DIMI)        // 160
#define NITEMS (NPROJ + NCROSS)      // 1672

// Precomputed small tables (scaling folded in)
__device__ float g_projH[HEADS * TABR];   // * INVT/3
__device__ float g_projW[HEADS * TABR];
__device__ float g_projD[HEADS * TABR];
__device__ float g_cross[HEADS * DIMI];   // * INVT

// One warp per output scalar: lane c handles elements c and c+32 of the
// 64-length dot product, then butterfly-reduce. Fires the PDL trigger once
// the tables are written so the dependent scores grid can proceed.
__global__ __launch_bounds__(256)
void prep_kernel(const float* __restrict__ enc_cross,
                 const float* __restrict__ enc_h,
                 const float* __restrict__ enc_w,
                 const float* __restrict__ enc_d,
                 const float* __restrict__ w_cross,
                 const float* __restrict__ w_h,
                 const float* __restrict__ w_w,
                 const float* __restrict__ w_d) {
    const int warp = blockIdx.x * 8 + (threadIdx.x >> 5);
    const int lane = threadIdx.x & 31;

    if (warp < NITEMS) {
        const float* vec;
        const float* w;
        float scale;
        float* dst;

        if (warp < NPROJ) {
            const int axis = warp / (HEADS * TABR);
            const int rem  = warp - axis * (HEADS * TABR);
            const int h = rem / TABR, r = rem - h * TABR;
            const float* tab = (axis == 0) ? enc_h : (axis == 1) ? enc_w : enc_d;
            const float* wt  = (axis == 0) ? w_h   : (axis == 1) ? w_w   : w_d;
            float* db        = (axis == 0) ? g_projH : (axis == 1) ? g_projW : g_projD;
            vec = tab + r * EMB;
            w   = wt + h * EMB;
            scale = INVT / 3.0f;
            dst = db + h * TABR + r;
        } else {
            const int rem = warp - NPROJ;
            const int h = rem / DIMI, n = rem - h * DIMI;
            vec = enc_cross + n * EMB;
            w   = w_cross + h * EMB;
            scale = INVT;
            dst = g_cross + h * DIMI + n;
        }

        float s = w[lane] * vec[lane] + w[lane + 32] * vec[lane + 32];
        #pragma unroll
        for (int off = 16; off > 0; off >>= 1)
            s += __shfl_xor_sync(0xffffffffu, s, off);
        if (lane == 0) *dst = s * scale;
    }

#if __CUDA_ARCH__ >= 900
    cudaTriggerProgrammaticLaunchCompletion();
#endif
}

// One block per output row (h, q), 256 threads.
// Content span f in [5, 1029) is exactly 1024 float4 = 4 branch-free
// iterations x 256 threads, with the D-axis values iteration-invariant.
__global__ __launch_bounds__(256)
void scores_kernel(float* __restrict__ out) {
    const int bid = blockIdx.x;              // h * NQ + q
    const int h = bid / NQ;
    const int q = bid - h * NQ;
    float4* __restrict__ row = reinterpret_cast<float4*>(out + (size_t)bid * NQ);
    const int t = threadIdx.x;

    if (q < DIMI) {
        // zero row: no tables needed, no PDL sync — overlaps with prep
        const float4 z = make_float4(0.f, 0.f, 0.f, 0.f);
        for (int f = t; f < ROWF4; f += 256) row[f] = z;
        return;
    }

#if __CUDA_ARCH__ >= 900
    cudaGridDependencySynchronize();
#endif

    __shared__ float sa[16], sb[16], sc[16], scr[DIMI];
    const int srow = q - DIMI;
    const int i  = srow >> 8;
    const int j  = (srow >> 4) & 15;
    const int k3 = srow & 15;

    if (t < 16)       sa[t]        = g_projH[h * TABR + (t)        - i  + 31];
    else if (t < 32)  sb[t - 16]   = g_projW[h * TABR + (t - 16)   - j  + 31];
    else if (t < 48)  sc[t - 32]   = g_projD[h * TABR + (t - 32)   - k3 + 31];
    else if (t < 48 + DIMI) scr[t - 48] = g_cross[h * DIMI + (t - 48)];
    __syncthreads();

    // Cross block: 5 float4s (k = 0..19), threads 0..4
    if (t < 5) {
        float4 v;
        v.x = scr[4 * t + 0];
        v.y = scr[4 * t + 1];
        v.z = scr[4 * t + 2];
        v.w = scr[4 * t + 3];
        row[t] = v;
    }

    // Content block: f = 5 + t + 256*it, it = 0..3 (exact, no tail).
    // scol = 4*f - 20 = 4*t + 1024*it  =>  n0 = (4*t) & 15 is loop-invariant.
    const int scol0 = 4 * t;
    const int n0 = scol0 & 15;
    const float c0 = sc[n0 + 0];
    const float c1 = sc[n0 + 1];
    const float c2 = sc[n0 + 2];
    const float c3 = sc[n0 + 3];

    #pragma unroll
    for (int it = 0; it < 4; it++) {
        const int scol = scol0 + 1024 * it;
        const int l = scol >> 8;
        const int m = (scol >> 4) & 15;
        const float base = sa[l] + sb[m];
        float4 v;
        v.x = base + c0;
        v.y = base + c1;
        v.z = base + c2;
        v.w = base + c3;
        row[5 + t + 256 * it] = v;
    }
}

extern "C" void kernel_launch(void* const* d_in, const int* in_sizes, int n_in,
                              void* d_out, int out_size) {
    const float* enc_cross = (const float*)d_in[0];
    const float* enc_h     = (const float*)d_in[1];
    const float* enc_w     = (const float*)d_in[2];
    const float* enc_d     = (const float*)d_in[3];
    const float* w_cross   = (const float*)d_in[4];
    const float* w_h       = (const float*)d_in[5];
    const float* w_w       = (const float*)d_in[6];
    const float* w_d       = (const float*)d_in[7];
    float* out = (float*)d_out;

    prep_kernel<<<(NITEMS + 7) / 8, 256>>>(enc_cross, enc_h, enc_w, enc_d,
                                           w_cross, w_h, w_w, w_d);

    // Dependent launch with programmatic stream serialization (PDL).
    cudaLaunchConfig_t cfg = {};
    cfg.gridDim  = dim3(HEADS * NQ);
    cfg.blockDim = dim3(256);
    cfg.dynamicSmemBytes = 0;
    cfg.stream = 0;
    cudaLaunchAttribute attr[1];
    attr[0].id = cudaLaunchAttributeProgrammaticStreamSerialization;
    attr[0].val.programmaticStreamSerializationAllowed = 1;
    cfg.attrs = attr;
    cfg.numAttrs = 1;
    cudaLaunchKernelEx(&cfg, scores_kernel, out);
}

// round 15
// speedup vs baseline: 1.0025x; 1.0025x over previous
#include <cuda_runtime.h>
#include <cuda_bf16.h>
#include <cstdint>

// Problem constants (fixed by the reference)
#define EMB    64
#define HEADS  8
#define DIMI   20
#define NQ     4116                  // DIMI + 16*16*16
#define ROWF4  1029                  // 4116 / 4
#define TABR   63                    // 2*CAP - 1
#define INVT   0.125f                // 64^-0.5

#define NPROJ  (3 * HEADS * TABR)    // 1512
#define NCROSS (HEADS * DIMI)        // 160
#define NITEMS (NPROJ + NCROSS)      // 1672

// Precomputed small tables (scaling folded in)
__device__ float g_projH[HEADS * TABR];   // * INVT/3
__device__ float g_projW[HEADS * TABR];
__device__ float g_projD[HEADS * TABR];
__device__ float g_cross[HEADS * DIMI];   // * INVT

// One warp per output scalar: lane c handles elements c and c+32 of the
// 64-length dot product, then butterfly-reduce. Fires the PDL trigger once
// the tables are written so the dependent scores grid can proceed.
__global__ __launch_bounds__(256)
void prep_kernel(const float* __restrict__ enc_cross,
                 const float* __restrict__ enc_h,
                 const float* __restrict__ enc_w,
                 const float* __restrict__ enc_d,
                 const float* __restrict__ w_cross,
                 const float* __restrict__ w_h,
                 const float* __restrict__ w_w,
                 const float* __restrict__ w_d) {
    const int warp = blockIdx.x * 8 + (threadIdx.x >> 5);
    const int lane = threadIdx.x & 31;

    if (warp < NITEMS) {
        const float* vec;
        const float* w;
        float scale;
        float* dst;

        if (warp < NPROJ) {
            const int axis = warp / (HEADS * TABR);
            const int rem  = warp - axis * (HEADS * TABR);
            const int h = rem / TABR, r = rem - h * TABR;
            const float* tab = (axis == 0) ? enc_h : (axis == 1) ? enc_w : enc_d;
            const float* wt  = (axis == 0) ? w_h   : (axis == 1) ? w_w   : w_d;
            float* db        = (axis == 0) ? g_projH : (axis == 1) ? g_projW : g_projD;
            vec = tab + r * EMB;
            w   = wt + h * EMB;
            scale = INVT / 3.0f;
            dst = db + h * TABR + r;
        } else {
            const int rem = warp - NPROJ;
            const int h = rem / DIMI, n = rem - h * DIMI;
            vec = enc_cross + n * EMB;
            w   = w_cross + h * EMB;
            scale = INVT;
            dst = g_cross + h * DIMI + n;
        }

        float s = w[lane] * vec[lane] + w[lane + 32] * vec[lane + 32];
        #pragma unroll
        for (int off = 16; off > 0; off >>= 1)
            s += __shfl_xor_sync(0xffffffffu, s, off);
        if (lane == 0) *dst = s * scale;
    }

#if __CUDA_ARCH__ >= 900
    cudaTriggerProgrammaticLaunchCompletion();
#endif
}

// One block per output row (h, q), 256 threads.
// Content span f in [5, 1029) is exactly 1024 float4 = 4 branch-free
// iterations x 256 threads, with the D-axis values iteration-invariant.
__global__ __launch_bounds__(256)
void scores_kernel(float* __restrict__ out) {
    const int bid = blockIdx.x;              // h * NQ + q
    const int h = bid / NQ;
    const int q = bid - h * NQ;
    float4* __restrict__ row = reinterpret_cast<float4*>(out + (size_t)bid * NQ);
    const int t = threadIdx.x;

    if (q < DIMI) {
        // zero row: no tables needed, no PDL sync — overlaps with prep
        const float4 z = make_float4(0.f, 0.f, 0.f, 0.f);
        for (int f = t; f < ROWF4; f += 256) row[f] = z;
        return;
    }

#if __CUDA_ARCH__ >= 900
    cudaGridDependencySynchronize();
#endif

    __shared__ float sa[16], sb[16], sc[16], scr[DIMI];
    const int srow = q - DIMI;
    const int i  = srow >> 8;
    const int j  = (srow >> 4) & 15;
    const int k3 = srow & 15;

    if (t < 16)       sa[t]        = g_projH[h * TABR + (t)        - i  + 31];
    else if (t < 32)  sb[t - 16]   = g_projW[h * TABR + (t - 16)   - j  + 31];
    else if (t < 48)  sc[t - 32]   = g_projD[h * TABR + (t - 32)   - k3 + 31];
    else if (t < 48 + DIMI) scr[t - 48] = g_cross[h * DIMI + (t - 48)];
    __syncthreads();

    // Cross block: 5 float4s (k = 0..19), threads 0..4
    if (t < 5) {
        float4 v;
        v.x = scr[4 * t + 0];
        v.y = scr[4 * t + 1];
        v.z = scr[4 * t + 2];
        v.w = scr[4 * t + 3];
        row[t] = v;
    }

    // Content block: f = 5 + t + 256*it, it = 0..3 (exact, no tail).
    // scol = 4*f - 20 = 4*t + 1024*it  =>  n0 = (4*t) & 15 is loop-invariant.
    const int scol0 = 4 * t;
    const int n0 = scol0 & 15;
    const float c0 = sc[n0 + 0];
    const float c1 = sc[n0 + 1];
    const float c2 = sc[n0 + 2];
    const float c3 = sc[n0 + 3];

    #pragma unroll
    for (int it = 0; it < 4; it++) {
        const int scol = scol0 + 1024 * it;
        const int l = scol >> 8;
        const int m = (scol >> 4) & 15;
        const float base = sa[l] + sb[m];
        float4 v;
        v.x = base + c0;
        v.y = base + c1;
        v.z = base + c2;
        v.w = base + c3;
        row[5 + t + 256 * it] = v;
    }
}

extern "C" void kernel_launch(void* const* d_in, const int* in_sizes, int n_in,
                              void* d_out, int out_size) {
    const float* enc_cross = (const float*)d_in[0];
    const float* enc_h     = (const float*)d_in[1];
    const float* enc_w     = (const float*)d_in[2];
    const float* enc_d     = (const float*)d_in[3];
    const float* w_cross   = (const float*)d_in[4];
    const float* w_h       = (const float*)d_in[5];
    const float* w_w       = (const float*)d_in[6];
    const float* w_d       = (const float*)d_in[7];
    float* out = (float*)d_out;

    prep_kernel<<<(NITEMS + 7) / 8, 256>>>(enc_cross, enc_h, enc_w, enc_d,
                                           w_cross, w_h, w_w, w_d);

    // Dependent launch with programmatic stream serialization (PDL).
    cudaLaunchConfig_t cfg = {};
    cfg.gridDim  = dim3(HEADS * NQ);
    cfg.blockDim = dim3(256);
    cfg.dynamicSmemBytes = 0;
    cfg.stream = 0;
    cudaLaunchAttribute attr[1];
    attr[0].id = cudaLaunchAttributeProgrammaticStreamSerialization;
    attr[0].val.programmaticStreamSerializationAllowed = 1;
    cfg.attrs = attr;
    cfg.numAttrs = 1;
    cudaLaunchKernelEx(&cfg, scores_kernel, out);
}